// round 5
// baseline (speedup 1.0000x reference)
#include <cuda_runtime.h>
#include <cuda_bf16.h>
#include <stdint.h>
#include <math.h>

// ===================== PTX helpers (base ISA only: sm_80+) =====================
__device__ __forceinline__ uint32_t smem_to_u32(const void* p) {
    uint32_t a;
    asm("{ .reg .u64 t; cvta.to.shared.u64 t, %1; cvt.u32.u64 %0, t; }" : "=r"(a) : "l"(p));
    return a;
}
#define CP16(sa, g) \
    asm volatile("cp.async.cg.shared.global [%0], [%1], 16;" :: "r"((uint32_t)(sa)), "l"(g) : "memory")
#define CP_COMMIT() asm volatile("cp.async.commit_group;" ::: "memory")
#define CP_WAIT(n)  asm volatile("cp.async.wait_group %0;" :: "n"(n) : "memory")

#define LDM4(r, addr) \
    asm volatile("ldmatrix.sync.aligned.m8n8.x4.shared.b16 {%0,%1,%2,%3}, [%4];" \
        : "=r"((r)[0]), "=r"((r)[1]), "=r"((r)[2]), "=r"((r)[3]) : "r"((uint32_t)(addr)))

#define MMA16816(d, a, b) \
    asm volatile("mma.sync.aligned.m16n8k16.row.col.f32.bf16.bf16.f32 " \
        "{%0,%1,%2,%3}, {%4,%5,%6,%7}, {%8,%9}, {%0,%1,%2,%3};" \
        : "+f"((d)[0]), "+f"((d)[1]), "+f"((d)[2]), "+f"((d)[3]) \
        : "r"((a)[0]), "r"((a)[1]), "r"((a)[2]), "r"((a)[3]), "r"((b)[0]), "r"((b)[1]))

// ===================== constants + scratch =====================
__constant__ int    c_C[4]    = {256, 512, 1024, 2048};
__constant__ int    c_KOFF[4] = {0, 256, 768, 1792};
__constant__ size_t c_offA[4] = {0, 2097152, 6291456, 14680064};
__constant__ size_t c_offW[4] = {0, 131072, 393216, 917504};

__device__ __align__(16) __nv_bfloat16 g_Abf[8192u * 3840u];
__device__ __align__(16) __nv_bfloat16 g_Wt[512u * 3840u];
__device__ __align__(16) float2 g_rowstat[4 * 8192];
__device__ __align__(16) float2 g_pmstat[4];
__device__ __align__(16) float  g_pm[3840];
__device__ float  g_tinv[8];
__device__ __align__(16) float  g_cvec[3 * 4 * 512];
__device__ __align__(16) float  g_cpart[4 * 32 * 3 * 512];
__device__ __align__(16) float  g_ss[16 * 8192];
__device__ __align__(16) float  g_dot[16u * 8192u * 8u];

// ===================== precompute =====================
// pooled fp32 -> bf16 + per-row {sum, sumsq}
__global__ void k_abf(const float* __restrict__ p0, const float* __restrict__ p1,
                      const float* __restrict__ p2, const float* __restrict__ p3) {
    int lvl = blockIdx.y, row = blockIdx.x;
    int C = c_C[lvl];
    const float* p = (lvl == 0) ? p0 : (lvl == 1) ? p1 : (lvl == 2) ? p2 : p3;
    const float2* src = (const float2*)(p + (size_t)row * C);
    __nv_bfloat162* dst = (__nv_bfloat162*)(g_Abf + c_offA[lvl] + (size_t)row * C);
    int n2 = C >> 1;
    float s = 0.f, q = 0.f;
    for (int i = threadIdx.x; i < n2; i += 128) {
        float2 v = src[i];
        s += v.x + v.y;
        q = fmaf(v.x, v.x, q); q = fmaf(v.y, v.y, q);
        dst[i] = __floats2bfloat162_rn(v.x, v.y);
    }
    #pragma unroll
    for (int o = 16; o > 0; o >>= 1) {
        s += __shfl_xor_sync(0xffffffffu, s, o);
        q += __shfl_xor_sync(0xffffffffu, q, o);
    }
    __shared__ float shs[4], shq[4];
    int w = threadIdx.x >> 5, l = threadIdx.x & 31;
    if (l == 0) { shs[w] = s; shq[w] = q; }
    __syncthreads();
    if (threadIdx.x == 0)
        g_rowstat[lvl * 8192 + row] = make_float2(shs[0] + shs[1] + shs[2] + shs[3],
                                                  shq[0] + shq[1] + shq[2] + shq[3]);
}

__global__ void k_pm(const float* __restrict__ pr0, const float* __restrict__ pr1,
                     const float* __restrict__ pr2, const float* __restrict__ pr3) {
    int j = blockIdx.x * blockDim.x + threadIdx.x;
    if (j >= 3840) return;
    int lvl, c;
    if (j < 256)       { lvl = 0; c = j; }
    else if (j < 768)  { lvl = 1; c = j - 256; }
    else if (j < 1792) { lvl = 2; c = j - 768; }
    else               { lvl = 3; c = j - 1792; }
    int C = c_C[lvl];
    const float* pr = (lvl == 0) ? pr0 : (lvl == 1) ? pr1 : (lvl == 2) ? pr2 : pr3;
    float s = 0.f;
    #pragma unroll 8
    for (int r = 0; r < 64; ++r) s += pr[r * C + c];
    g_pm[j] = s * (1.0f / 64.0f);
}

__global__ void k_pmstat() {
    int lvl = blockIdx.x;
    int C = c_C[lvl], koff = c_KOFF[lvl];
    __shared__ float s1[256], s2[256];
    float a = 0.f, b = 0.f;
    for (int c = threadIdx.x; c < C; c += 256) {
        float v = g_pm[koff + c];
        a += v; b = fmaf(v, v, b);
    }
    s1[threadIdx.x] = a; s2[threadIdx.x] = b;
    __syncthreads();
    for (int st = 128; st > 0; st >>= 1) {
        if (threadIdx.x < st) { s1[threadIdx.x] += s1[threadIdx.x + st]; s2[threadIdx.x] += s2[threadIdx.x + st]; }
        __syncthreads();
    }
    if (threadIdx.x == 0) g_pmstat[lvl] = make_float2(s1[0], s2[0]);
}

__global__ void k_tnorm(const float* __restrict__ text) {
    int wid = threadIdx.x >> 5, lane = threadIdx.x & 31;
    if (wid >= 8) return;
    float s = 0.f;
    for (int i = lane; i < 512; i += 32) {
        float v = text[wid * 512 + i];
        s = fmaf(v, v, s);
    }
    #pragma unroll
    for (int o = 16; o > 0; o >>= 1) s += __shfl_xor_sync(0xffffffffu, s, o);
    if (lane == 0) g_tinv[wid] = 1.0f / fmaxf(sqrtf(s), 1e-12f);
}

// Wt[lvl][n][k] = g[k] * W[k*512+n]  (k < C: lower-half weight, g1 = g[0:C])
__global__ void k_wt(const float* __restrict__ W0, const float* __restrict__ W1,
                     const float* __restrict__ W2, const float* __restrict__ W3,
                     const float* __restrict__ g0, const float* __restrict__ g1,
                     const float* __restrict__ g2, const float* __restrict__ g3) {
    int blk = blockIdx.x;
    int lvl, tb;
    if (blk < 128)      { lvl = 0; tb = blk; }
    else if (blk < 384) { lvl = 1; tb = blk - 128; }
    else if (blk < 896) { lvl = 2; tb = blk - 384; }
    else                { lvl = 3; tb = blk - 896; }
    int C = c_C[lvl];
    int k0 = (tb >> 4) * 32;
    int n0 = (tb & 15) * 32;
    const float* W = (lvl == 0) ? W0 : (lvl == 1) ? W1 : (lvl == 2) ? W2 : W3;
    const float* g = (lvl == 0) ? g0 : (lvl == 1) ? g1 : (lvl == 2) ? g2 : g3;
    __shared__ float tile[32][33];
    __shared__ float gb[32];
    int tx = threadIdx.x & 31, ty = threadIdx.x >> 5;
    if (threadIdx.x < 32) gb[threadIdx.x] = g[k0 + threadIdx.x];
    #pragma unroll
    for (int rr = 0; rr < 4; ++rr) {
        int kk = ty + rr * 8;
        tile[kk][tx] = W[(size_t)(k0 + kk) * 512 + n0 + tx];
    }
    __syncthreads();
    #pragma unroll
    for (int rr = 0; rr < 4; ++rr) {
        int nn = ty + rr * 8;
        g_Wt[c_offW[lvl] + (size_t)(n0 + nn) * C + k0 + tx] = __float2bfloat16(gb[tx] * tile[tx][nn]);
    }
}

// c-vector partials over 128-wide j segments of [0, 2C)
__global__ void k_cpart(const float* __restrict__ W0, const float* __restrict__ W1,
                        const float* __restrict__ W2, const float* __restrict__ W3,
                        const float* __restrict__ g0, const float* __restrict__ g1,
                        const float* __restrict__ g2, const float* __restrict__ g3,
                        const float* __restrict__ q0, const float* __restrict__ q1,
                        const float* __restrict__ q2, const float* __restrict__ q3) {
    int blk = blockIdx.x;
    int lvl, seg;
    if (blk < 4)       { lvl = 0; seg = blk; }
    else if (blk < 12) { lvl = 1; seg = blk - 4; }
    else if (blk < 28) { lvl = 2; seg = blk - 12; }
    else               { lvl = 3; seg = blk - 28; }
    int C = c_C[lvl];
    const float* W  = (lvl == 0) ? W0 : (lvl == 1) ? W1 : (lvl == 2) ? W2 : W3;
    const float* g  = (lvl == 0) ? g0 : (lvl == 1) ? g1 : (lvl == 2) ? g2 : g3;
    const float* bb = (lvl == 0) ? q0 : (lvl == 1) ? q1 : (lvl == 2) ? q2 : q3;
    int d = threadIdx.x;
    int j0 = seg * 128;
    bool upper = (j0 >= C);
    int koff = c_KOFF[lvl];
    float a1 = 0.f, a2 = 0.f, a3 = 0.f;
    #pragma unroll 4
    for (int jj = 0; jj < 128; ++jj) {
        int j = j0 + jj;
        float w = W[(size_t)j * 512 + d];
        float gj = g[j];
        a2 = fmaf(gj, w, a2);
        a3 = fmaf(bb[j], w, a3);
        if (upper) a1 = fmaf(g_pm[koff + j - C] * gj, w, a1);
    }
    size_t o = (size_t)(lvl * 32 + seg) * 3 * 512 + d;
    g_cpart[o] = a1; g_cpart[o + 512] = a2; g_cpart[o + 1024] = a3;
}

__global__ void k_cred(const float* __restrict__ b0, const float* __restrict__ b1,
                       const float* __restrict__ b2, const float* __restrict__ b3) {
    int lvl = blockIdx.x, d = threadIdx.x;
    int nseg = c_C[lvl] >> 6;   // 2C/128
    float a1 = 0.f, a2 = 0.f, a3 = 0.f;
    for (int s = 0; s < nseg; ++s) {
        size_t o = (size_t)(lvl * 32 + s) * 3 * 512 + d;
        a1 += g_cpart[o]; a2 += g_cpart[o + 512]; a3 += g_cpart[o + 1024];
    }
    const float* b = (lvl == 0) ? b0 : (lvl == 1) ? b1 : (lvl == 2) ? b2 : b3;
    g_cvec[(0 * 4 + lvl) * 512 + d] = a1;
    g_cvec[(1 * 4 + lvl) * 512 + d] = a2;
    g_cvec[(2 * 4 + lvl) * 512 + d] = a3 + b[d];
}

// ===================== GEMM (mma.sync bf16) + fused epilogue =====================
// CTA = 128 rows x 128 cols, 8 warps (4M x 2N), warp tile 32x64, BK=32.
// smem rows padded to 80B (40 bf16): conflict-free-enough ldmatrix, 16B-aligned cp.async.
static constexpr int STG       = 20480;           // A 10240 + B 10240
static constexpr int OFF_ROWC  = 4 * STG;         // 81920: float2[128]
static constexpr int OFF_CC    = OFF_ROWC + 1024; // 82944: float[3][128]
static constexpr int OFF_TX    = OFF_CC + 1536;   // 84480: float[8][128]
static constexpr int OFF_SPAR  = OFF_TX + 4096;   // 88576: float[128][2][10]
static constexpr int SMEM_REQ  = OFF_SPAR + 10240; // 98816

__global__ void __launch_bounds__(256) k_gemm(const float* __restrict__ text) {
    extern __shared__ char sm[];
    uint32_t base = smem_to_u32(sm);
    int tid = threadIdx.x, lane = tid & 31, wid = tid >> 5;
    int wm = wid >> 1, wn = wid & 1;

    int bid = blockIdx.x;
    int lvl = 3 - (bid >> 8);          // heavy levels first
    int r = bid & 255;
    int m0 = (r >> 2) << 7;
    int q = r & 3;                     // 128-col chunk of the 512 output dims
    int C = c_C[lvl];
    int nc = C >> 5;                   // K chunks of 32

    float2* rowcS = (float2*)(sm + OFF_ROWC);
    float*  ccS   = (float*)(sm + OFF_CC);
    float*  txS   = (float*)(sm + OFF_TX);
    float*  sparS = (float*)(sm + OFF_SPAR);

    const __nv_bfloat16* Ab = g_Abf + c_offA[lvl];
    const __nv_bfloat16* Bb = g_Wt + c_offW[lvl] + (size_t)(q * 128) * C;

    // cp.async: 512 16B-slots per tile; thread handles slot tid and tid+256
    int s0 = tid, s1 = tid + 256;
    const __nv_bfloat16* gA0 = Ab + (size_t)(m0 + (s0 >> 2)) * C + (s0 & 3) * 8;
    const __nv_bfloat16* gA1 = Ab + (size_t)(m0 + (s1 >> 2)) * C + (s1 & 3) * 8;
    const __nv_bfloat16* gB0 = Bb + (size_t)(s0 >> 2) * C + (s0 & 3) * 8;
    const __nv_bfloat16* gB1 = Bb + (size_t)(s1 >> 2) * C + (s1 & 3) * 8;
    uint32_t aOff0 = (uint32_t)((s0 >> 2) * 80 + (s0 & 3) * 16);
    uint32_t aOff1 = (uint32_t)((s1 >> 2) * 80 + (s1 & 3) * 16);

    auto load_chunk = [&](int c, int s) {
        uint32_t st = base + s * STG;
        int ko = c << 5;
        CP16(st + aOff0, gA0 + ko);
        CP16(st + aOff1, gA1 + ko);
        CP16(st + 10240 + aOff0, gB0 + ko);
        CP16(st + 10240 + aOff1, gB1 + ko);
        CP_COMMIT();
    };

    load_chunk(0, 0); load_chunk(1, 1); load_chunk(2, 2);

    // column/row constants (disjoint smem; visible after first __syncthreads)
    if (tid < 128) {
        int d = tid;
        ccS[d]       = g_cvec[(0 * 4 + lvl) * 512 + q * 128 + d];
        ccS[128 + d] = g_cvec[(1 * 4 + lvl) * 512 + q * 128 + d];
        ccS[256 + d] = g_cvec[(2 * 4 + lvl) * 512 + q * 128 + d];
        #pragma unroll
        for (int k = 0; k < 8; ++k) txS[k * 128 + d] = text[k * 512 + q * 128 + d];
        float2 sq = g_rowstat[lvl * 8192 + m0 + d];
        float2 pq = g_pmstat[lvl];
        float inv2C = 0.5f / (float)C;
        float mm = (sq.x + pq.x) * inv2C;
        float vv = (sq.y + pq.y) * inv2C - mm * mm;
        float rsv = rsqrtf(vv + 1e-5f);
        rowcS[d] = make_float2(rsv, mm * rsv);
    }

    float acc[2][8][4];
    #pragma unroll
    for (int i = 0; i < 2; ++i)
        #pragma unroll
        for (int j = 0; j < 8; ++j)
            #pragma unroll
            for (int v = 0; v < 4; ++v) acc[i][j][v] = 0.f;

    uint32_t aBase = (uint32_t)((wm * 32 + (lane & 15)) * 80 + (lane >> 4) * 16);
    uint32_t bBase = (uint32_t)(10240 +
                     (wn * 64 + ((lane >> 4) << 3) + (lane & 7)) * 80 +
                     ((lane >> 3) & 1) * 16);

    for (int c = 0; c < nc; ++c) {
        int pend = nc - 1 - c;
        if (pend >= 2)      CP_WAIT(2);
        else if (pend == 1) CP_WAIT(1);
        else                CP_WAIT(0);
        __syncthreads();
        if (c + 3 < nc) load_chunk(c + 3, (c + 3) & 3);

        uint32_t st = base + (c & 3) * STG;
        #pragma unroll
        for (int ks = 0; ks < 2; ++ks) {
            uint32_t af[2][4];
            #pragma unroll
            for (int mf = 0; mf < 2; ++mf)
                LDM4(af[mf], st + aBase + mf * (16 * 80) + ks * 32);
            uint32_t bf[8][2];
            #pragma unroll
            for (int nf2 = 0; nf2 < 4; ++nf2) {
                uint32_t t4[4];
                LDM4(t4, st + bBase + nf2 * (16 * 80) + ks * 32);
                bf[nf2 * 2][0] = t4[0]; bf[nf2 * 2][1] = t4[1];
                bf[nf2 * 2 + 1][0] = t4[2]; bf[nf2 * 2 + 1][1] = t4[3];
            }
            #pragma unroll
            for (int mf = 0; mf < 2; ++mf)
                #pragma unroll
                for (int nf = 0; nf < 8; ++nf)
                    MMA16816(acc[mf][nf], af[mf], bf[nf]);
        }
    }

    // ===== fused epilogue: LN + relu + sumsq + 8 text dots, all in registers =====
    float2 rst[4];
    {
        int rb = wm * 32 + (lane >> 2);
        #pragma unroll
        for (int i = 0; i < 4; ++i) rst[i] = rowcS[rb + i * 8];  // rows +0,+8,+16,+24
    }
    float ssv[4];
    float dtv[4][8];
    #pragma unroll
    for (int i = 0; i < 4; ++i) {
        ssv[i] = 0.f;
        #pragma unroll
        for (int k = 0; k < 8; ++k) dtv[i][k] = 0.f;
    }
    const float2* cc1 = (const float2*)(ccS);
    const float2* cc2 = (const float2*)(ccS + 128);
    const float2* cc3 = (const float2*)(ccS + 256);
    const float2* tx2 = (const float2*)(txS);

    #pragma unroll
    for (int nf = 0; nf < 8; ++nf) {
        int cp = ((wn * 64 + nf * 8) >> 1) + (lane & 3);   // float2 index: cols 2cp, 2cp+1
        float2 v1 = cc1[cp], v2 = cc2[cp], v3 = cc3[cp];
        float2 tt[8];
        #pragma unroll
        for (int k = 0; k < 8; ++k) tt[k] = tx2[k * 64 + cp];
        #pragma unroll
        for (int mf = 0; mf < 2; ++mf) {
            #pragma unroll
            for (int rr = 0; rr < 2; ++rr) {
                int i = mf * 2 + rr;       // rows wm*32 + mf*16 + rr*8 + lane>>2
                float rsv = rst[i].x, mrs = rst[i].y;
                float a0 = acc[mf][nf][rr * 2 + 0];
                float a1 = acc[mf][nf][rr * 2 + 1];
                float h0 = fmaxf(fmaf(rsv, a0 + v1.x, fmaf(-mrs, v2.x, v3.x)), 0.f);
                float h1 = fmaxf(fmaf(rsv, a1 + v1.y, fmaf(-mrs, v2.y, v3.y)), 0.f);
                ssv[i] = fmaf(h0, h0, fmaf(h1, h1, ssv[i]));
                #pragma unroll
                for (int k = 0; k < 8; ++k)
                    dtv[i][k] = fmaf(h0, tt[k].x, fmaf(h1, tt[k].y, dtv[i][k]));
            }
        }
    }
    // quad reduce (lanes sharing a row differ only in lane&3)
    #pragma unroll
    for (int i = 0; i < 4; ++i) {
        float s = ssv[i];
        s += __shfl_xor_sync(0xffffffffu, s, 1);
        s += __shfl_xor_sync(0xffffffffu, s, 2);
        ssv[i] = s;
        #pragma unroll
        for (int k = 0; k < 8; ++k) {
            float dd = dtv[i][k];
            dd += __shfl_xor_sync(0xffffffffu, dd, 1);
            dd += __shfl_xor_sync(0xffffffffu, dd, 2);
            dtv[i][k] = dd;
        }
    }
    if ((lane & 3) == 0) {
        #pragma unroll
        for (int i = 0; i < 4; ++i) {
            int row = wm * 32 + (i >> 1) * 16 + (i & 1) * 8 + (lane >> 2);
            float* p = sparS + (row * 2 + wn) * 10;
            p[0] = ssv[i];
            #pragma unroll
            for (int k = 0; k < 8; ++k) p[1 + k] = dtv[i][k];
        }
    }
    __syncthreads();
    if (tid < 128) {
        int row = tid;
        const float* p0 = sparS + (row * 2 + 0) * 10;
        const float* p1 = sparS + (row * 2 + 1) * 10;
        size_t ob = (size_t)((lvl * 4 + q) * 8192 + m0 + row);
        g_ss[ob] = p0[0] + p1[0];
        #pragma unroll
        for (int k = 0; k < 8; ++k) g_dot[ob * 8 + k] = p0[1 + k] + p1[1 + k];
    }
}

// ===================== output: norm + scale + softmax =====================
__global__ void k_out(float* __restrict__ out, const float* __restrict__ scale_p) {
    int t = blockIdx.x * blockDim.x + threadIdx.x;   // 65536 = 8192*8
    int b = t >> 3, k = t & 7;
    float cs = fmaxf(scale_p[0], 1e-4f) * 0.044194173824159216f * g_tinv[k];
    float sc[4];
    #pragma unroll
    for (int l = 0; l < 4; ++l) {
        float n2 = 0.f, d = 0.f;
        #pragma unroll
        for (int qq = 0; qq < 4; ++qq) {
            size_t ob = (size_t)((l * 4 + qq) * 8192 + b);
            n2 += g_ss[ob];
            d += g_dot[ob * 8 + k];
        }
        float nrm = fmaxf(sqrtf(n2), 1e-12f);
        sc[l] = d / nrm * cs;
    }
    float mx = fmaxf(fmaxf(sc[0], sc[1]), fmaxf(sc[2], sc[3]));
    float e0 = __expf(sc[0] - mx), e1 = __expf(sc[1] - mx);
    float e2 = __expf(sc[2] - mx), e3 = __expf(sc[3] - mx);
    float inv = 1.0f / (e0 + e1 + e2 + e3);
    ((float4*)out)[t] = make_float4(e0 * inv, e1 * inv, e2 * inv, e3 * inv);
}

// ===================== launch =====================
extern "C" void kernel_launch(void* const* d_in, const int* in_sizes, int n_in,
                              void* d_out, int out_size) {
    static const int Cs[4] = {256, 512, 1024, 2048};
    long expA[26];
    {
        int idx = 0;
        for (int i = 0; i < 4; ++i) {
            long C = Cs[i];
            expA[idx++] = 8192L * C; expA[idx++] = 64L * C;
            expA[idx++] = 2L * C;    expA[idx++] = 2L * C;
            expA[idx++] = 2L * C * 512L; expA[idx++] = 512L;
        }
        expA[24] = 4096; expA[25] = 1;
    }
    bool inter = (n_in == 26);
    if (inter)
        for (int i = 0; i < 26; ++i)
            if ((long)in_sizes[i] != expA[i]) { inter = false; break; }

    const float *pooled[4], *proto[4], *lng[4], *lnb[4], *W[4], *bv[4];
    const float *text, *scale;
    if (inter) {
        for (int l = 0; l < 4; ++l) {
            int b6 = 6 * l;
            pooled[l] = (const float*)d_in[b6 + 0];
            proto[l]  = (const float*)d_in[b6 + 1];
            lng[l]    = (const float*)d_in[b6 + 2];
            lnb[l]    = (const float*)d_in[b6 + 3];
            W[l]      = (const float*)d_in[b6 + 4];
            bv[l]     = (const float*)d_in[b6 + 5];
        }
        text  = (const float*)d_in[24];
        scale = (const float*)d_in[25];
    } else {
        for (int l = 0; l < 4; ++l) {
            pooled[l] = (const float*)d_in[l];
            proto[l]  = (const float*)d_in[4 + l];
            lng[l]    = (const float*)d_in[8 + l];
            lnb[l]    = (const float*)d_in[12 + l];
            W[l]      = (const float*)d_in[16 + l];
            bv[l]     = (const float*)d_in[20 + l];
        }
        text  = (const float*)d_in[24];
        scale = (const float*)d_in[25];
    }

    cudaFuncSetAttribute(k_gemm, cudaFuncAttributeMaxDynamicSharedMemorySize, SMEM_REQ);

    k_pm<<<15, 256>>>(proto[0], proto[1], proto[2], proto[3]);
    k_pmstat<<<4, 256>>>();
    k_tnorm<<<1, 256>>>(text);
    k_wt<<<1920, 256>>>(W[0], W[1], W[2], W[3], lng[0], lng[1], lng[2], lng[3]);
    k_cpart<<<60, 512>>>(W[0], W[1], W[2], W[3],
                         lng[0], lng[1], lng[2], lng[3],
                         lnb[0], lnb[1], lnb[2], lnb[3]);
    k_cred<<<4, 512>>>(bv[0], bv[1], bv[2], bv[3]);
    {
        dim3 g(8192, 4);
        k_abf<<<g, 128>>>(pooled[0], pooled[1], pooled[2], pooled[3]);
    }
    k_gemm<<<1024, 256, SMEM_REQ>>>(text);
    k_out<<<256, 256>>>((float*)d_out, scale);
}